// round 3
// baseline (speedup 1.0000x reference)
#include <cuda_runtime.h>
#include <cuda_bf16.h>
#include <math.h>

// DBN downbeat Viterbi on a single persistent CTA.
//
// Per frame t:
//   v_new[s]        = v[s-1] + dens_t[class(s)]                (non-first states)
//   v_new[first_bj] = max_i( v[prev_last[b,i]] + LT[b,i,j] ) + dens_t[class]
// Only the 240 first-state backpointers are data-dependent (others are s-1),
// so backtrace is run-length decodable from a per-frame 240-entry bp table.

#define MAXF   6016
#define MAXBT  256
#define NT     768

__device__ float          g_dens[MAXF * 3];
__device__ int            g_bpf[MAXF * MAXBT];
__device__ unsigned short g_bj[32768];

// ------------------------------------------------------------------
// observation log-densities, all frames in parallel
// ------------------------------------------------------------------
__global__ void setup_kernel(const float* __restrict__ acts, int F)
{
    int t = blockIdx.x * blockDim.x + threadIdx.x;
    if (t < F) {
        float ab = acts[2 * t + 0];
        float ad = acts[2 * t + 1];
        // match reference op order: ((1.0 - a_b) - a_d) / 15.0
        g_dens[3 * t + 0] = logf(((1.0f - ab) - ad) / 15.0f);
        g_dens[3 * t + 1] = logf(ab);
        g_dens[3 * t + 2] = logf(ad);
    }
}

// ------------------------------------------------------------------
// persistent single-block Viterbi + backtrace
// ------------------------------------------------------------------
__global__ __launch_bounds__(NT, 1)
void viterbi_kernel(const float* __restrict__ lt_g,   // [4,T,T] log transition
                    const int*   __restrict__ pl_g,   // prev_last [4,T]
                    const int*   __restrict__ fs_g,   // first_states [4,T]
                    const int*   __restrict__ ptr_g,  // pointer [S] (class 0..2)
                    int S, int T, int F,
                    float* outF, int* outI, int outMode, int outSize)
{
    extern __shared__ unsigned char sm[];
    const int Sp  = (S + 3) & ~3;
    const int ltN = 4 * T * T;

    float* vA    = (float*)sm;            // Sp
    float* vB    = vA + Sp;               // Sp
    float* ltS   = vB + Sp;               // ltN
    float* cand  = ltS + ltN;             // MAXBT
    float* densS = cand + MAXBT;          // 8
    float* redV  = densS + 8;             // NT
    int*   redIs = (int*)(redV + NT);     // NT
    int*   plS   = redIs + NT;            // MAXBT
    int*   fsS   = plS + MAXBT;           // MAXBT
    unsigned char* cls = (unsigned char*)(fsS + MAXBT);  // Sp bytes

    const int tid = threadIdx.x;
    const int nBT = 4 * T;                // 240
    const float v0 = -logf((float)S);

    // ---- prologue ----
    for (int s = tid; s < ltN; s += NT) ltS[s] = lt_g[s];
    for (int s = tid; s < S; s += NT) {
        vA[s]  = v0;
        cls[s] = (unsigned char)ptr_g[s];
    }
    if (tid < nBT) { plS[tid] = pl_g[tid]; fsS[tid] = fs_g[tid]; }
    __syncthreads();

    int rb = 0, rj = 0, rfs = 0, rcf = 0;
    if (tid < nBT) {
        rb  = tid / T;
        rj  = tid - rb * T;
        rfs = fsS[tid];
        rcf = ptr_g[rfs];                        // class of the first state
        cls[rfs] = (unsigned char)(rcf | 4);     // mark as first
        // build state -> (b,j) map for backtrace; last_states[b] = prev_last[(b+1)%4]
        int lastS = pl_g[(((rb + 1) & 3) * T) + rj];
        for (int s = rfs; s <= lastS; ++s) g_bj[s] = (unsigned short)tid;
    }
    __syncthreads();

    // ---- main frame loop ----
    float* vCur = vA;
    float* vNxt = vB;
    for (int t = 0; t < F; ++t) {
        // stage A: gather candidates + this frame's densities
        if (tid < nBT) cand[tid] = vCur[plS[tid]];
        if (tid >= NT - 3) densS[tid - (NT - 3)] = g_dens[3 * t + (tid - (NT - 3))];
        __syncthreads();

        // stage B
        if (tid < nBT) {
            // 60-wide max-plus reduction for output (rb, rj)
            const float* col = ltS + (rb * T) * T + rj;   // stride T over i
            const float* cb  = cand + rb * T;
            float best = cb[0] + col[0];
            int   arg  = 0;
            for (int i = 1; i < T; ++i) {
                float sc = cb[i] + col[i * T];
                if (sc > best) { best = sc; arg = i; }    // strict > == first argmax
            }
            g_bpf[(t << 8) + tid] = plS[rb * T + arg];
            float d = (rcf == 0) ? densS[0] : ((rcf == 1) ? densS[1] : densS[2]);
            vNxt[rfs] = best + d;
        } else {
            // shift-sweep over non-first states
            const float d0 = densS[0], d1 = densS[1], d2 = densS[2];
            for (int s = tid - nBT; s < S; s += (NT - nBT)) {
                unsigned char m = cls[s];
                if (!(m & 4)) {
                    int c = m & 3;
                    float d = (c == 0) ? d0 : ((c == 1) ? d1 : d2);
                    vNxt[s] = vCur[s - 1] + d;
                }
            }
        }
        __syncthreads();
        float* tmp = vCur; vCur = vNxt; vNxt = tmp;
    }

    // ---- final argmax (first occurrence on ties) ----
    float bv = -3.0e38f;
    int   bi = 0x7fffffff;
    for (int s = tid; s < S; s += NT) {
        float v = vCur[s];
        if (v > bv) { bv = v; bi = s; }   // ascending within stride-class
    }
    redV[tid] = bv; redIs[tid] = bi;
    __syncthreads();

    if (tid == 0) {
        for (int k = 1; k < NT; ++k) {
            float v = redV[k]; int i = redIs[k];
            if (v > bv || (v == bv && i < bi)) { bv = v; bi = i; }
        }

        // ---- backtrace with run-length decoding ----
        int s = bi;
        int t = F - 1;
        if (outMode) outF[t] = (float)s; else outI[t] = s;
        while (t > 0) {
            int bj  = g_bj[s];
            int fsv = fsS[bj];
            if (s > fsv) {
                int k = s - fsv; if (k > t) k = t;
                if (outMode) { for (int m = 1; m <= k; ++m) outF[t - m] = (float)(s - m); }
                else         { for (int m = 1; m <= k; ++m) outI[t - m] = s - m; }
                s -= k; t -= k;
            } else {
                s = g_bpf[(t << 8) + bj];
                --t;
                if (outMode) outF[t] = (float)s; else outI[t] = s;
            }
        }
        if (outMode && outSize > F) outF[F] = bv;   // logp
    }
}

// ------------------------------------------------------------------
extern "C" void kernel_launch(void* const* d_in, const int* in_sizes, int n_in,
                              void* d_out, int out_size)
{
    const float* acts = (const float*)d_in[0];   // [F,2]
    const float* lt   = (const float*)d_in[1];   // [4,T,T]
    const int*   pl   = (const int*)d_in[2];     // [4,T]
    const int*   fs   = (const int*)d_in[3];     // [4,T]
    const int*   ptr  = (const int*)d_in[4];     // [S]

    const int F = in_sizes[0] / 2;
    const int T = in_sizes[2] / 4;
    const int S = in_sizes[4];
    const int Sp  = (S + 3) & ~3;
    const int ltN = 4 * T * T;

    size_t smemBytes =
        (size_t)4 * (2 * Sp + ltN + MAXBT + 8 + NT + NT + MAXBT + MAXBT)
        + (size_t)Sp + 16;

    int outMode = (out_size == F) ? 0 : 1;   // F -> int path only; F+1 -> float path+logp

    cudaFuncSetAttribute(viterbi_kernel,
                         cudaFuncAttributeMaxDynamicSharedMemorySize,
                         (int)smemBytes);

    setup_kernel<<<(F + 255) / 256, 256>>>(acts, F);
    viterbi_kernel<<<1, NT, smemBytes>>>(lt, pl, fs, ptr, S, T, F,
                                         (float*)d_out, (int*)d_out,
                                         outMode, out_size);
}

// round 4
// speedup vs baseline: 1.7601x; 1.7601x over previous
#include <cuda_runtime.h>
#include <cuda_bf16.h>
#include <math.h>

// DBN downbeat Viterbi, single persistent CTA, all hot state in SMEM/registers.
//
// Per frame t:
//   v_new[s]        = v[s-1] + dens_t[class(s)]                (non-first states)
//   v_new[first_bj] = max_i( v[prev_last[b,i]] + LT[b,i,j] ) + dens_t[class]
// Only the 240 first-state backpointers are data-dependent (others are s-1),
// so backtrace is run-length decodable from a per-frame 240-entry bp table.

#define MAXBT   256
#define NT      768
#define MAXBAND 36
#define KMAXC   24      // max states per thread (S <= NT*KMAXC)

__device__ int            g_bpf[6016 * MAXBT];
__device__ unsigned short g_bj[32768];

__global__ __launch_bounds__(NT, 1)
void viterbi_kernel(const float* __restrict__ acts,   // [F,2]
                    const float* __restrict__ lt_g,   // [4,T,T]
                    const int*   __restrict__ pl_g,   // prev_last [4,T]
                    const int*   __restrict__ fs_g,   // first_states [4,T]
                    const int*   __restrict__ ptr_g,  // pointer [S]
                    int S, int T, int F,
                    float* outF, int* outI, int outMode, int outSize)
{
    extern __shared__ unsigned char sm[];
    const int Sp = (S + 3) & ~3;

    float* vA    = (float*)sm;                 // Sp
    float* vB    = vA + Sp;                    // Sp
    float* dAll  = vB + Sp;                    // 3*F
    float* cand  = dAll + 3 * F;               // MAXBT
    int*   plS   = (int*)(cand + MAXBT);       // MAXBT
    int*   fsS   = plS + MAXBT;                // MAXBT
    float* redV  = (float*)(fsS + MAXBT);      // NT
    int*   redIs = (int*)(redV + NT);          // NT
    unsigned char* cls = (unsigned char*)(redIs + NT);  // Sp bytes

    const int tid    = threadIdx.x;
    const int warpId = tid >> 5;
    const int nBT    = 4 * T;                        // 240
    const int redWarps = (nBT + 31) >> 5;            // 8
    const int barCnt   = redWarps << 5;              // 256
    const bool isRed   = (tid < nBT);
    const int kmax     = (S + NT - 1) / NT;          // ~20

    // ---------------- prologue ----------------
    // densities for ALL frames -> SMEM (match reference op order exactly)
    for (int t = tid; t < F; t += NT) {
        float ab = acts[2 * t + 0];
        float ad = acts[2 * t + 1];
        dAll[3 * t + 0] = logf(((1.0f - ab) - ad) / 15.0f);
        dAll[3 * t + 1] = logf(ab);
        dAll[3 * t + 2] = logf(ad);
    }
    const float v0 = -logf((float)S);
    for (int s = tid; s < S; s += NT) {
        vA[s]  = v0;
        cls[s] = (unsigned char)ptr_g[s];
    }
    if (tid < nBT) { plS[tid] = pl_g[tid]; fsS[tid] = fs_g[tid]; }
    __syncthreads();

    // reduction-thread private state
    int rb = 0, rj = 0, rfs = 0, rcf = 0, plReg = 0, cbase = 0, lo = 0, W = 0;
    const float* colG = lt_g;
    float LTreg[MAXBAND];
    if (isRed) {
        rb    = tid / T;
        rj    = tid - rb * T;
        rfs   = fsS[tid];
        rcf   = ptr_g[rfs];
        plReg = plS[tid];
        cbase = rb * T;
        cls[rfs] = (unsigned char)(rcf | 4);          // mark first state
        colG  = lt_g + (rb * T) * T + rj;             // column j of beat b, stride T
        int loi = -1, hii = -1;
        for (int i = 0; i < T; ++i) {
            float x = colG[i * T];
            if (x > -1e29f) { if (loi < 0) loi = i; hii = i; }
        }
        lo = loi; W = hii - loi + 1;
#pragma unroll
        for (int k = 0; k < MAXBAND; ++k)
            LTreg[k] = (k < W) ? colG[(lo + k) * T] : -1e30f;
        // state -> (b,j) map for backtrace; last_states[b] = prev_last[(b+1)%4]
        int lastS = pl_g[(((rb + 1) & 3) * T) + rj];
        for (int s = rfs; s <= lastS; ++s) g_bj[s] = (unsigned short)tid;
    }
    __syncthreads();

    // pack per-thread sweep metadata into registers (states s = tid + k*NT)
    unsigned m1 = 0, m2 = 0, skip = 0;
#pragma unroll
    for (int k = 0; k < KMAXC; ++k) {
        int s = tid + k * NT;
        if (k >= kmax || s >= S || s == 0) { skip |= 1u << k; continue; }
        unsigned char m = cls[s];
        if (m & 4) { skip |= 1u << k; continue; }      // first state: reduction writes it
        unsigned c = m & 3u;
        if (c == 1) m1 |= 1u << k;
        else if (c == 2) m2 |= 1u << k;
    }
    __syncthreads();

    // ---------------- main frame loop ----------------
    float* vCur = vA;
    float* vNxt = vB;
    for (int t = 0; t < F; ++t) {
        const float d0 = dAll[3 * t + 0];
        const float d1 = dAll[3 * t + 1];
        const float d2 = dAll[3 * t + 2];

        if (isRed) cand[tid] = vCur[plReg];
        if (warpId < redWarps)
            asm volatile("bar.sync 1, %0;" :: "r"(barCnt) : "memory");

        if (isRed) {
            // banded max-plus reduction, strict > ascending == first argmax
            float best = cand[cbase + lo] + LTreg[0];
            int   arg  = lo;
#pragma unroll
            for (int k = 1; k < MAXBAND; ++k) {
                if (k < W) {
                    float sc = cand[cbase + lo + k] + LTreg[k];
                    bool p = sc > best;
                    best = p ? sc : best;
                    arg  = p ? (lo + k) : arg;
                }
            }
            for (int k = MAXBAND; k < W; ++k) {        // safety tail (normally empty)
                float sc = cand[cbase + lo + k] + colG[(lo + k) * T];
                bool p = sc > best;
                best = p ? sc : best;
                arg  = p ? (lo + k) : arg;
            }
            g_bpf[(t << 8) + tid] = plS[cbase + arg];
            float df = (rcf == 1) ? d1 : ((rcf == 2) ? d2 : d0);
            vNxt[rfs] = best + df;
        }

        // shift-sweep (all threads), strided -> conflict-free LDS/STS
#pragma unroll 4
        for (int k = 0; k < kmax; ++k) {
            if (!((skip >> k) & 1u)) {
                int s = tid + k * NT;
                float d = ((m1 >> k) & 1u) ? d1 : (((m2 >> k) & 1u) ? d2 : d0);
                vNxt[s] = vCur[s - 1] + d;
            }
        }
        __syncthreads();
        float* tmp = vCur; vCur = vNxt; vNxt = tmp;
    }

    // ---------------- final argmax (first occurrence on ties) ----------------
    float bv = -3.0e38f;
    int   bi = 0x7fffffff;
    for (int s = tid; s < S; s += NT) {
        float v = vCur[s];
        if (v > bv) { bv = v; bi = s; }
    }
    redV[tid] = bv; redIs[tid] = bi;
    __syncthreads();

    if (tid == 0) {
        for (int k = 1; k < NT; ++k) {
            float v = redV[k]; int i = redIs[k];
            if (v > bv || (v == bv && i < bi)) { bv = v; bi = i; }
        }
        // backtrace with run-length decoding
        int s = bi;
        int t = F - 1;
        if (outMode) outF[t] = (float)s; else outI[t] = s;
        while (t > 0) {
            int bj  = g_bj[s];
            int fsv = fsS[bj];
            if (s > fsv) {
                int k = s - fsv; if (k > t) k = t;
                if (outMode) { for (int m = 1; m <= k; ++m) outF[t - m] = (float)(s - m); }
                else         { for (int m = 1; m <= k; ++m) outI[t - m] = s - m; }
                s -= k; t -= k;
            } else {
                s = g_bpf[(t << 8) + bj];
                --t;
                if (outMode) outF[t] = (float)s; else outI[t] = s;
            }
        }
        if (outMode && outSize > F) outF[F] = bv;
    }
}

// ------------------------------------------------------------------
extern "C" void kernel_launch(void* const* d_in, const int* in_sizes, int n_in,
                              void* d_out, int out_size)
{
    const float* acts = (const float*)d_in[0];   // [F,2]
    const float* lt   = (const float*)d_in[1];   // [4,T,T]
    const int*   pl   = (const int*)d_in[2];     // [4,T]
    const int*   fs   = (const int*)d_in[3];     // [4,T]
    const int*   ptr  = (const int*)d_in[4];     // [S]

    const int F  = in_sizes[0] / 2;
    const int T  = in_sizes[2] / 4;
    const int S  = in_sizes[4];
    const int Sp = (S + 3) & ~3;

    size_t smemBytes =
        (size_t)4 * (2 * Sp + 3 * F + MAXBT + MAXBT + MAXBT + NT + NT)
        + (size_t)Sp + 64;

    int outMode = (out_size == F) ? 0 : 1;

    cudaFuncSetAttribute(viterbi_kernel,
                         cudaFuncAttributeMaxDynamicSharedMemorySize,
                         (int)smemBytes);

    viterbi_kernel<<<1, NT, smemBytes>>>(acts, lt, pl, fs, ptr, S, T, F,
                                         (float*)d_out, (int*)d_out,
                                         outMode, out_size);
}

// round 6
// speedup vs baseline: 1.7601x; 1.0000x over previous
#include <cuda_runtime.h>
#include <cuda_bf16.h>
#include <math.h>

// DBN downbeat Viterbi, single persistent CTA, all hot state in SMEM/registers.
//
// Per frame t:
//   v_new[s]        = v[s-1] + dens_t[class(s)]                (non-first states)
//   v_new[first_bj] = max_i( v[prev_last[b,i]] + LT[b,i,j] ) + dens_t[class]
// Only the 240 first-state backpointers are data-dependent (others are s-1),
// so backtrace is run-length decodable from a per-frame 240-entry bp table.

#define MAXBT   256
#define NT      768
#define MAXBAND 36
#define KMAXC   24      // max states per thread (S <= NT*KMAXC)

__device__ int            g_bpf[6016 * MAXBT];
__device__ unsigned short g_bj[32768];

__global__ __launch_bounds__(NT, 1)
void viterbi_kernel(const float* __restrict__ acts,   // [F,2]
                    const float* __restrict__ lt_g,   // [4,T,T]
                    const int*   __restrict__ pl_g,   // prev_last [4,T]
                    const int*   __restrict__ fs_g,   // first_states [4,T]
                    const int*   __restrict__ ptr_g,  // pointer [S]
                    int S, int T, int F,
                    float* outF, int* outI, int outMode, int outSize)
{
    extern __shared__ unsigned char sm[];
    const int Sp = (S + 3) & ~3;

    float* vA    = (float*)sm;                 // Sp
    float* vB    = vA + Sp;                    // Sp
    float* dAll  = vB + Sp;                    // 3*F
    float* cand  = dAll + 3 * F;               // MAXBT
    int*   plS   = (int*)(cand + MAXBT);       // MAXBT
    int*   fsS   = plS + MAXBT;                // MAXBT
    float* redV  = (float*)(fsS + MAXBT);      // NT
    int*   redIs = (int*)(redV + NT);          // NT
    unsigned char* cls = (unsigned char*)(redIs + NT);  // Sp bytes

    const int tid    = threadIdx.x;
    const int warpId = tid >> 5;
    const int nBT    = 4 * T;                        // 240
    const int redWarps = (nBT + 31) >> 5;            // 8
    const int barCnt   = redWarps << 5;              // 256
    const bool isRed   = (tid < nBT);
    const int kmax     = (S + NT - 1) / NT;          // ~20

    // ---------------- prologue ----------------
    // densities for ALL frames -> SMEM (match reference op order exactly)
    for (int t = tid; t < F; t += NT) {
        float ab = acts[2 * t + 0];
        float ad = acts[2 * t + 1];
        dAll[3 * t + 0] = logf(((1.0f - ab) - ad) / 15.0f);
        dAll[3 * t + 1] = logf(ab);
        dAll[3 * t + 2] = logf(ad);
    }
    const float v0 = -logf((float)S);
    for (int s = tid; s < S; s += NT) {
        vA[s]  = v0;
        cls[s] = (unsigned char)ptr_g[s];
    }
    if (tid < nBT) { plS[tid] = pl_g[tid]; fsS[tid] = fs_g[tid]; }
    __syncthreads();

    // reduction-thread private state
    int rb = 0, rj = 0, rfs = 0, rcf = 0, plReg = 0, cbase = 0, lo = 0, W = 0;
    const float* colG = lt_g;
    float LTreg[MAXBAND];
    if (isRed) {
        rb    = tid / T;
        rj    = tid - rb * T;
        rfs   = fsS[tid];
        rcf   = ptr_g[rfs];
        plReg = plS[tid];
        cbase = rb * T;
        cls[rfs] = (unsigned char)(rcf | 4);          // mark first state
        colG  = lt_g + (rb * T) * T + rj;             // column j of beat b, stride T
        int loi = -1, hii = -1;
        for (int i = 0; i < T; ++i) {
            float x = colG[i * T];
            if (x > -1e29f) { if (loi < 0) loi = i; hii = i; }
        }
        lo = loi; W = hii - loi + 1;
#pragma unroll
        for (int k = 0; k < MAXBAND; ++k)
            LTreg[k] = (k < W) ? colG[(lo + k) * T] : -1e30f;
        // state -> (b,j) map for backtrace; last_states[b] = prev_last[(b+1)%4]
        int lastS = pl_g[(((rb + 1) & 3) * T) + rj];
        for (int s = rfs; s <= lastS; ++s) g_bj[s] = (unsigned short)tid;
    }
    __syncthreads();

    // pack per-thread sweep metadata into registers (states s = tid + k*NT)
    unsigned m1 = 0, m2 = 0, skip = 0;
#pragma unroll
    for (int k = 0; k < KMAXC; ++k) {
        int s = tid + k * NT;
        if (k >= kmax || s >= S || s == 0) { skip |= 1u << k; continue; }
        unsigned char m = cls[s];
        if (m & 4) { skip |= 1u << k; continue; }      // first state: reduction writes it
        unsigned c = m & 3u;
        if (c == 1) m1 |= 1u << k;
        else if (c == 2) m2 |= 1u << k;
    }
    __syncthreads();

    // ---------------- main frame loop ----------------
    float* vCur = vA;
    float* vNxt = vB;
    for (int t = 0; t < F; ++t) {
        const float d0 = dAll[3 * t + 0];
        const float d1 = dAll[3 * t + 1];
        const float d2 = dAll[3 * t + 2];

        if (isRed) cand[tid] = vCur[plReg];
        if (warpId < redWarps)
            asm volatile("bar.sync 1, %0;" :: "r"(barCnt) : "memory");

        if (isRed) {
            // banded max-plus reduction, strict > ascending == first argmax
            float best = cand[cbase + lo] + LTreg[0];
            int   arg  = lo;
#pragma unroll
            for (int k = 1; k < MAXBAND; ++k) {
                if (k < W) {
                    float sc = cand[cbase + lo + k] + LTreg[k];
                    bool p = sc > best;
                    best = p ? sc : best;
                    arg  = p ? (lo + k) : arg;
                }
            }
            for (int k = MAXBAND; k < W; ++k) {        // safety tail (normally empty)
                float sc = cand[cbase + lo + k] + colG[(lo + k) * T];
                bool p = sc > best;
                best = p ? sc : best;
                arg  = p ? (lo + k) : arg;
            }
            g_bpf[(t << 8) + tid] = plS[cbase + arg];
            float df = (rcf == 1) ? d1 : ((rcf == 2) ? d2 : d0);
            vNxt[rfs] = best + df;
        }

        // shift-sweep (all threads), strided -> conflict-free LDS/STS
#pragma unroll 4
        for (int k = 0; k < kmax; ++k) {
            if (!((skip >> k) & 1u)) {
                int s = tid + k * NT;
                float d = ((m1 >> k) & 1u) ? d1 : (((m2 >> k) & 1u) ? d2 : d0);
                vNxt[s] = vCur[s - 1] + d;
            }
        }
        __syncthreads();
        float* tmp = vCur; vCur = vNxt; vNxt = tmp;
    }

    // ---------------- final argmax (first occurrence on ties) ----------------
    float bv = -3.0e38f;
    int   bi = 0x7fffffff;
    for (int s = tid; s < S; s += NT) {
        float v = vCur[s];
        if (v > bv) { bv = v; bi = s; }
    }
    redV[tid] = bv; redIs[tid] = bi;
    __syncthreads();

    if (tid == 0) {
        for (int k = 1; k < NT; ++k) {
            float v = redV[k]; int i = redIs[k];
            if (v > bv || (v == bv && i < bi)) { bv = v; bi = i; }
        }
        // backtrace with run-length decoding
        int s = bi;
        int t = F - 1;
        if (outMode) outF[t] = (float)s; else outI[t] = s;
        while (t > 0) {
            int bj  = g_bj[s];
            int fsv = fsS[bj];
            if (s > fsv) {
                int k = s - fsv; if (k > t) k = t;
                if (outMode) { for (int m = 1; m <= k; ++m) outF[t - m] = (float)(s - m); }
                else         { for (int m = 1; m <= k; ++m) outI[t - m] = s - m; }
                s -= k; t -= k;
            } else {
                s = g_bpf[(t << 8) + bj];
                --t;
                if (outMode) outF[t] = (float)s; else outI[t] = s;
            }
        }
        if (outMode && outSize > F) outF[F] = bv;
    }
}

// ------------------------------------------------------------------
extern "C" void kernel_launch(void* const* d_in, const int* in_sizes, int n_in,
                              void* d_out, int out_size)
{
    const float* acts = (const float*)d_in[0];   // [F,2]
    const float* lt   = (const float*)d_in[1];   // [4,T,T]
    const int*   pl   = (const int*)d_in[2];     // [4,T]
    const int*   fs   = (const int*)d_in[3];     // [4,T]
    const int*   ptr  = (const int*)d_in[4];     // [S]

    const int F  = in_sizes[0] / 2;
    const int T  = in_sizes[2] / 4;
    const int S  = in_sizes[4];
    const int Sp = (S + 3) & ~3;

    size_t smemBytes =
        (size_t)4 * (2 * Sp + 3 * F + MAXBT + MAXBT + MAXBT + NT + NT)
        + (size_t)Sp + 64;

    int outMode = (out_size == F) ? 0 : 1;

    cudaFuncSetAttribute(viterbi_kernel,
                         cudaFuncAttributeMaxDynamicSharedMemorySize,
                         (int)smemBytes);

    viterbi_kernel<<<1, NT, smemBytes>>>(acts, lt, pl, fs, ptr, S, T, F,
                                         (float*)d_out, (int*)d_out,
                                         outMode, out_size);
}

// round 10
// speedup vs baseline: 2.1860x; 1.2420x over previous
#include <cuda_runtime.h>
#include <cuda_bf16.h>
#include <math.h>

// DBN downbeat Viterbi, single persistent CTA.
// v kept in SMEM double-buffer; sweep vectorized with interleaved quad
// ownership: thread tid, slot g owns states [4*(tid + g*NT), +4).
// LDS.128/STS.128 conflict-free; shift-by-1 via shfl + register recombine.

#define MAXBT   256
#define NT      768
#define QPT     5            // quads per thread -> capacity 4*NT*QPT = 15360
#define CAP     (4 * NT * QPT)
#define MAXBAND 36

__device__ int            g_bpf[6016 * MAXBT];
__device__ unsigned short g_bj[32768];

__global__ __launch_bounds__(NT, 1)
void viterbi_kernel(const float* __restrict__ acts,   // [F,2]
                    const float* __restrict__ lt_g,   // [4,T,T]
                    const int*   __restrict__ pl_g,   // prev_last [4,T]
                    const int*   __restrict__ fs_g,   // first_states [4,T]
                    const int*   __restrict__ ptr_g,  // pointer [S]
                    int S, int T, int F,
                    float* outF, int* outI, int outMode, int outSize)
{
    extern __shared__ unsigned char sm[];
    float* dAll  = (float*)sm;                     // 3*F
    float* vA    = dAll + 3 * F;                   // CAP
    float* vB    = vA + CAP;                       // CAP
    float* cand  = vB + CAP;                       // MAXBT
    int*   plS   = (int*)(cand + MAXBT);           // MAXBT
    int*   fsS   = plS + MAXBT;                    // MAXBT
    float* redV  = (float*)(fsS + MAXBT);          // NT
    int*   redIs = (int*)(redV + NT);              // NT
    unsigned char* cls = (unsigned char*)(redIs + NT);  // S bytes

    const int tid  = threadIdx.x;
    const int lane = tid & 31;
    const int nBT  = 4 * T;                        // 240
    const bool isRed = (tid < nBT);

    // ---------------- prologue ----------------
    for (int t = tid; t < F; t += NT) {
        float ab = acts[2 * t + 0];
        float ad = acts[2 * t + 1];
        dAll[3 * t + 0] = logf(((1.0f - ab) - ad) / 15.0f);   // exact ref order
        dAll[3 * t + 1] = logf(ab);
        dAll[3 * t + 2] = logf(ad);
    }
    const float v0 = -logf((float)S);
    for (int s = tid; s < CAP; s += NT) vA[s] = v0;           // pad incl.
    for (int s = tid; s < S; s += NT) cls[s] = (unsigned char)ptr_g[s];
    if (tid < nBT) { plS[tid] = pl_g[tid]; fsS[tid] = fs_g[tid]; }
    __syncthreads();

    int rb = 0, rfs = 0, rcf = 0, plReg = 0, cbase = 0, lo = 0, W = 0;
    const float* colG = lt_g;
    float LTreg[MAXBAND];
    if (isRed) {
        rb    = tid / T;
        int rj = tid - rb * T;
        rfs   = fsS[tid];
        rcf   = ptr_g[rfs];
        plReg = plS[tid];
        cbase = rb * T;
        cls[rfs] |= 4;                              // mark first state
        colG  = lt_g + (rb * T) * T + rj;           // column j of beat b
        int loi = -1, hii = -1;
        for (int i = 0; i < T; ++i) {
            float x = colG[i * T];
            if (x > -1e29f) { if (loi < 0) loi = i; hii = i; }
        }
        lo = loi; W = hii - loi + 1;
#pragma unroll
        for (int k = 0; k < MAXBAND; ++k)
            LTreg[k] = (k < W) ? colG[(lo + k) * T] : -1e30f;
        int lastS = pl_g[(((rb + 1) & 3) * T) + rj];
        for (int s = rfs; s <= lastS; ++s) g_bj[s] = (unsigned short)tid;
    }
    __syncthreads();

    // per-thread sweep metadata: bit b = g*4+j -> state 4*(tid+g*NT)+j
    unsigned m1 = 0, m2 = 0, okM = 0;
#pragma unroll
    for (int g = 0; g < QPT; ++g)
#pragma unroll
        for (int j = 0; j < 4; ++j) {
            int b = g * 4 + j;
            int s = 4 * (tid + g * NT) + j;
            if (s < S) {
                unsigned char m = cls[s];
                if (!(m & 4) && s != 0) {
                    okM |= 1u << b;
                    unsigned c = m & 3u;
                    if (c == 1) m1 |= 1u << b;
                    else if (c == 2) m2 |= 1u << b;
                }
            }
        }
    // state 0 is a first state (reduction writes it); okM bit stays 0 there.
    __syncthreads();

    // ---------------- main frame loop ----------------
    float* vCur = vA;
    float* vNxt = vB;
    for (int t = 0; t < F; ++t) {
        const float d0 = dAll[3 * t + 0];
        const float d1 = dAll[3 * t + 1];
        const float d2 = dAll[3 * t + 2];

        if (isRed) cand[tid] = vCur[plReg];
        __syncthreads();                            // cand visible to reduction

        if (isRed) {
            // banded max-plus reduction, strict > ascending == first argmax
            float best = cand[cbase + lo] + LTreg[0];
            int   arg  = lo;
#pragma unroll
            for (int k = 1; k < MAXBAND; ++k) {
                if (k < W) {
                    float sc = cand[cbase + lo + k] + LTreg[k];
                    bool p = sc > best;
                    best = p ? sc : best;
                    arg  = p ? (lo + k) : arg;
                }
            }
            for (int k = MAXBAND; k < W; ++k) {      // safety tail (normally empty)
                float sc = cand[cbase + lo + k] + colG[(lo + k) * T];
                bool p = sc > best;
                best = p ? sc : best;
                arg  = p ? (lo + k) : arg;
            }
            g_bpf[(t << 8) + tid] = plS[cbase + arg];
            float df = (rcf == 1) ? d1 : ((rcf == 2) ? d2 : d0);
            vNxt[rfs] = best + df;
        }

        // vectorized shift-sweep
#pragma unroll
        for (int g = 0; g < QPT; ++g) {
            const int base = 4 * (tid + g * NT);
            float4 Q = *(const float4*)(vCur + base);
            float wl = __shfl_up_sync(0xffffffffu, Q.w, 1);
            if (lane == 0) wl = vCur[base - 1];     // base==0 -> dead value, bit off
            const int b0 = 4 * g;
            float e0 = ((m1 >> (b0+0)) & 1u) ? d1 : (((m2 >> (b0+0)) & 1u) ? d2 : d0);
            float e1 = ((m1 >> (b0+1)) & 1u) ? d1 : (((m2 >> (b0+1)) & 1u) ? d2 : d0);
            float e2 = ((m1 >> (b0+2)) & 1u) ? d1 : (((m2 >> (b0+2)) & 1u) ? d2 : d0);
            float e3 = ((m1 >> (b0+3)) & 1u) ? d1 : (((m2 >> (b0+3)) & 1u) ? d2 : d0);
            float4 Nq;
            Nq.x = wl  + e0;
            Nq.y = Q.x + e1;
            Nq.z = Q.y + e2;
            Nq.w = Q.z + e3;
            unsigned nib = (okM >> b0) & 0xFu;
            if (nib == 0xFu) {
                *(float4*)(vNxt + base) = Nq;
            } else if (nib) {
                if (nib & 1u) vNxt[base + 0] = Nq.x;
                if (nib & 2u) vNxt[base + 1] = Nq.y;
                if (nib & 4u) vNxt[base + 2] = Nq.z;
                if (nib & 8u) vNxt[base + 3] = Nq.w;
            }
        }
        __syncthreads();
        float* tmp = vCur; vCur = vNxt; vNxt = tmp;
    }

    // ---------------- final argmax (first occurrence on ties) ----------------
    float bv = -3.0e38f;
    int   bi = 0x7fffffff;
    for (int s = tid; s < S; s += NT) {
        float v = vCur[s];
        if (v > bv) { bv = v; bi = s; }
    }
    redV[tid] = bv; redIs[tid] = bi;
    __syncthreads();

    if (tid == 0) {
        for (int k = 1; k < NT; ++k) {
            float v = redV[k]; int i = redIs[k];
            if (v > bv || (v == bv && i < bi)) { bv = v; bi = i; }
        }
        // backtrace with run-length decoding
        int s = bi;
        int t = F - 1;
        if (outMode) outF[t] = (float)s; else outI[t] = s;
        while (t > 0) {
            int bj  = g_bj[s];
            int fsv = fsS[bj];
            if (s > fsv) {
                int k = s - fsv; if (k > t) k = t;
                if (outMode) { for (int m = 1; m <= k; ++m) outF[t - m] = (float)(s - m); }
                else         { for (int m = 1; m <= k; ++m) outI[t - m] = s - m; }
                s -= k; t -= k;
            } else {
                s = g_bpf[(t << 8) + bj];
                --t;
                if (outMode) outF[t] = (float)s; else outI[t] = s;
            }
        }
        if (outMode && outSize > F) outF[F] = bv;
    }
}

// ------------------------------------------------------------------
extern "C" void kernel_launch(void* const* d_in, const int* in_sizes, int n_in,
                              void* d_out, int out_size)
{
    const float* acts = (const float*)d_in[0];   // [F,2]
    const float* lt   = (const float*)d_in[1];   // [4,T,T]
    const int*   pl   = (const int*)d_in[2];     // [4,T]
    const int*   fs   = (const int*)d_in[3];     // [4,T]
    const int*   ptr  = (const int*)d_in[4];     // [S]

    const int F = in_sizes[0] / 2;
    const int T = in_sizes[2] / 4;
    const int S = in_sizes[4];

    size_t smemBytes =
        (size_t)4 * (3 * F)            // dAll
      + (size_t)4 * CAP * 2            // vA, vB
      + (size_t)4 * (MAXBT * 3)        // cand, plS, fsS
      + (size_t)4 * (NT * 2)           // redV, redIs
      + (size_t)S + 64;                // cls + pad

    int outMode = (out_size == F) ? 0 : 1;

    cudaFuncSetAttribute(viterbi_kernel,
                         cudaFuncAttributeMaxDynamicSharedMemorySize,
                         (int)smemBytes);

    viterbi_kernel<<<1, NT, smemBytes>>>(acts, lt, pl, fs, ptr, S, T, F,
                                         (float*)d_out, (int*)d_out,
                                         outMode, out_size);
}

// round 11
// speedup vs baseline: 2.3087x; 1.0561x over previous
#include <cuda_runtime.h>
#include <cuda_bf16.h>
#include <math.h>

// DBN downbeat Viterbi, single persistent CTA.
// v kept in SMEM double-buffer; sweep vectorized with interleaved quad
// ownership: thread tid, slot g owns states [4*(tid + g*NT), +4).
// LDS.128/STS.128 conflict-free; shift-by-1 via shfl + register recombine.

#define MAXBT   256
#define NT      768
#define QPT     5            // quads per thread -> capacity 4*NT*QPT = 15360
#define CAP     (4 * NT * QPT)
#define MAXBAND 36

__device__ int            g_bpf[6016 * MAXBT];
__device__ unsigned short g_bj[32768];

__global__ __launch_bounds__(NT, 1)
void viterbi_kernel(const float* __restrict__ acts,   // [F,2]
                    const float* __restrict__ lt_g,   // [4,T,T]
                    const int*   __restrict__ pl_g,   // prev_last [4,T]
                    const int*   __restrict__ fs_g,   // first_states [4,T]
                    const int*   __restrict__ ptr_g,  // pointer [S]
                    int S, int T, int F,
                    float* outF, int* outI, int outMode, int outSize)
{
    extern __shared__ unsigned char sm[];
    float* dAll  = (float*)sm;                     // 3*F
    float* vA    = dAll + 3 * F;                   // CAP
    float* vB    = vA + CAP;                       // CAP
    float* cand  = vB + CAP;                       // MAXBT
    int*   plS   = (int*)(cand + MAXBT);           // MAXBT
    int*   fsS   = plS + MAXBT;                    // MAXBT
    float* redV  = (float*)(fsS + MAXBT);          // NT
    int*   redIs = (int*)(redV + NT);              // NT
    unsigned char* cls = (unsigned char*)(redIs + NT);  // S bytes

    const int tid  = threadIdx.x;
    const int lane = tid & 31;
    const int nBT  = 4 * T;                        // 240
    const bool isRed = (tid < nBT);

    // ---------------- prologue ----------------
    for (int t = tid; t < F; t += NT) {
        float ab = acts[2 * t + 0];
        float ad = acts[2 * t + 1];
        dAll[3 * t + 0] = logf(((1.0f - ab) - ad) / 15.0f);   // exact ref order
        dAll[3 * t + 1] = logf(ab);
        dAll[3 * t + 2] = logf(ad);
    }
    const float v0 = -logf((float)S);
    for (int s = tid; s < CAP; s += NT) vA[s] = v0;           // pad incl.
    for (int s = tid; s < S; s += NT) cls[s] = (unsigned char)ptr_g[s];
    if (tid < nBT) { plS[tid] = pl_g[tid]; fsS[tid] = fs_g[tid]; }
    __syncthreads();

    int rb = 0, rfs = 0, rcf = 0, plReg = 0, cbase = 0, lo = 0, W = 0;
    const float* colG = lt_g;
    float LTreg[MAXBAND];
    if (isRed) {
        rb    = tid / T;
        int rj = tid - rb * T;
        rfs   = fsS[tid];
        rcf   = ptr_g[rfs];
        plReg = plS[tid];
        cbase = rb * T;
        cls[rfs] |= 4;                              // mark first state
        colG  = lt_g + (rb * T) * T + rj;           // column j of beat b
        int loi = -1, hii = -1;
        for (int i = 0; i < T; ++i) {
            float x = colG[i * T];
            if (x > -1e29f) { if (loi < 0) loi = i; hii = i; }
        }
        lo = loi; W = hii - loi + 1;
#pragma unroll
        for (int k = 0; k < MAXBAND; ++k)
            LTreg[k] = (k < W) ? colG[(lo + k) * T] : -1e30f;
        int lastS = pl_g[(((rb + 1) & 3) * T) + rj];
        for (int s = rfs; s <= lastS; ++s) g_bj[s] = (unsigned short)tid;
    }
    __syncthreads();

    // per-thread sweep metadata: bit b = g*4+j -> state 4*(tid+g*NT)+j
    unsigned m1 = 0, m2 = 0, okM = 0;
#pragma unroll
    for (int g = 0; g < QPT; ++g)
#pragma unroll
        for (int j = 0; j < 4; ++j) {
            int b = g * 4 + j;
            int s = 4 * (tid + g * NT) + j;
            if (s < S) {
                unsigned char m = cls[s];
                if (!(m & 4) && s != 0) {
                    okM |= 1u << b;
                    unsigned c = m & 3u;
                    if (c == 1) m1 |= 1u << b;
                    else if (c == 2) m2 |= 1u << b;
                }
            }
        }
    // state 0 is a first state (reduction writes it); okM bit stays 0 there.
    __syncthreads();

    // ---------------- main frame loop ----------------
    float* vCur = vA;
    float* vNxt = vB;
    for (int t = 0; t < F; ++t) {
        const float d0 = dAll[3 * t + 0];
        const float d1 = dAll[3 * t + 1];
        const float d2 = dAll[3 * t + 2];

        if (isRed) cand[tid] = vCur[plReg];
        __syncthreads();                            // cand visible to reduction

        if (isRed) {
            // banded max-plus reduction, strict > ascending == first argmax
            float best = cand[cbase + lo] + LTreg[0];
            int   arg  = lo;
#pragma unroll
            for (int k = 1; k < MAXBAND; ++k) {
                if (k < W) {
                    float sc = cand[cbase + lo + k] + LTreg[k];
                    bool p = sc > best;
                    best = p ? sc : best;
                    arg  = p ? (lo + k) : arg;
                }
            }
            for (int k = MAXBAND; k < W; ++k) {      // safety tail (normally empty)
                float sc = cand[cbase + lo + k] + colG[(lo + k) * T];
                bool p = sc > best;
                best = p ? sc : best;
                arg  = p ? (lo + k) : arg;
            }
            g_bpf[(t << 8) + tid] = plS[cbase + arg];
            float df = (rcf == 1) ? d1 : ((rcf == 2) ? d2 : d0);
            vNxt[rfs] = best + df;
        }

        // vectorized shift-sweep
#pragma unroll
        for (int g = 0; g < QPT; ++g) {
            const int base = 4 * (tid + g * NT);
            float4 Q = *(const float4*)(vCur + base);
            float wl = __shfl_up_sync(0xffffffffu, Q.w, 1);
            if (lane == 0) wl = vCur[base - 1];     // base==0 -> dead value, bit off
            const int b0 = 4 * g;
            float e0 = ((m1 >> (b0+0)) & 1u) ? d1 : (((m2 >> (b0+0)) & 1u) ? d2 : d0);
            float e1 = ((m1 >> (b0+1)) & 1u) ? d1 : (((m2 >> (b0+1)) & 1u) ? d2 : d0);
            float e2 = ((m1 >> (b0+2)) & 1u) ? d1 : (((m2 >> (b0+2)) & 1u) ? d2 : d0);
            float e3 = ((m1 >> (b0+3)) & 1u) ? d1 : (((m2 >> (b0+3)) & 1u) ? d2 : d0);
            float4 Nq;
            Nq.x = wl  + e0;
            Nq.y = Q.x + e1;
            Nq.z = Q.y + e2;
            Nq.w = Q.z + e3;
            unsigned nib = (okM >> b0) & 0xFu;
            if (nib == 0xFu) {
                *(float4*)(vNxt + base) = Nq;
            } else if (nib) {
                if (nib & 1u) vNxt[base + 0] = Nq.x;
                if (nib & 2u) vNxt[base + 1] = Nq.y;
                if (nib & 4u) vNxt[base + 2] = Nq.z;
                if (nib & 8u) vNxt[base + 3] = Nq.w;
            }
        }
        __syncthreads();
        float* tmp = vCur; vCur = vNxt; vNxt = tmp;
    }

    // ---------------- final argmax (first occurrence on ties) ----------------
    float bv = -3.0e38f;
    int   bi = 0x7fffffff;
    for (int s = tid; s < S; s += NT) {
        float v = vCur[s];
        if (v > bv) { bv = v; bi = s; }
    }
    redV[tid] = bv; redIs[tid] = bi;
    __syncthreads();

    if (tid == 0) {
        for (int k = 1; k < NT; ++k) {
            float v = redV[k]; int i = redIs[k];
            if (v > bv || (v == bv && i < bi)) { bv = v; bi = i; }
        }
        // backtrace with run-length decoding
        int s = bi;
        int t = F - 1;
        if (outMode) outF[t] = (float)s; else outI[t] = s;
        while (t > 0) {
            int bj  = g_bj[s];
            int fsv = fsS[bj];
            if (s > fsv) {
                int k = s - fsv; if (k > t) k = t;
                if (outMode) { for (int m = 1; m <= k; ++m) outF[t - m] = (float)(s - m); }
                else         { for (int m = 1; m <= k; ++m) outI[t - m] = s - m; }
                s -= k; t -= k;
            } else {
                s = g_bpf[(t << 8) + bj];
                --t;
                if (outMode) outF[t] = (float)s; else outI[t] = s;
            }
        }
        if (outMode && outSize > F) outF[F] = bv;
    }
}

// ------------------------------------------------------------------
extern "C" void kernel_launch(void* const* d_in, const int* in_sizes, int n_in,
                              void* d_out, int out_size)
{
    const float* acts = (const float*)d_in[0];   // [F,2]
    const float* lt   = (const float*)d_in[1];   // [4,T,T]
    const int*   pl   = (const int*)d_in[2];     // [4,T]
    const int*   fs   = (const int*)d_in[3];     // [4,T]
    const int*   ptr  = (const int*)d_in[4];     // [S]

    const int F = in_sizes[0] / 2;
    const int T = in_sizes[2] / 4;
    const int S = in_sizes[4];

    size_t smemBytes =
        (size_t)4 * (3 * F)            // dAll
      + (size_t)4 * CAP * 2            // vA, vB
      + (size_t)4 * (MAXBT * 3)        // cand, plS, fsS
      + (size_t)4 * (NT * 2)           // redV, redIs
      + (size_t)S + 64;                // cls + pad

    int outMode = (out_size == F) ? 0 : 1;

    cudaFuncSetAttribute(viterbi_kernel,
                         cudaFuncAttributeMaxDynamicSharedMemorySize,
                         (int)smemBytes);

    viterbi_kernel<<<1, NT, smemBytes>>>(acts, lt, pl, fs, ptr, S, T, F,
                                         (float*)d_out, (int*)d_out,
                                         outMode, out_size);
}

// round 12
// speedup vs baseline: 2.4081x; 1.0431x over previous
#include <cuda_runtime.h>
#include <cuda_bf16.h>
#include <math.h>

// DBN downbeat Viterbi, single persistent CTA.
// Sweep: interleaved quad ownership (thread tid, slot g owns states
// [4*(tid+g*NT), +4)), LDS.128/STS.128 conflict-free, shift via shfl.
// Pure class-0 quads take a 9-instr path; quads containing special states
// (class!=0 / first / >=S) are computed-but-discarded, their real states
// written by compacted handler slots (built once in prologue).

#define MAXBT   256
#define NT      768
#define QPT     5            // quads per thread -> capacity 4*NT*QPT = 15360
#define CAP     (4 * NT * QPT)
#define MAXBAND 36
#define HSLOTS  5            // handler slots per thread (cap 5*NT = 3840)

__device__ int            g_bpf[6016 * MAXBT];
__device__ unsigned short g_bj[32768];
__device__ int            g_hlist[HSLOTS * NT];

__global__ __launch_bounds__(NT, 1)
void viterbi_kernel(const float* __restrict__ acts,   // [F,2]
                    const float* __restrict__ lt_g,   // [4,T,T]
                    const int*   __restrict__ pl_g,   // prev_last [4,T]
                    const int*   __restrict__ fs_g,   // first_states [4,T]
                    const int*   __restrict__ ptr_g,  // pointer [S]
                    int S, int T, int F,
                    float* outF, int* outI, int outMode, int outSize)
{
    extern __shared__ unsigned char sm[];
    float* dAll  = (float*)sm;                     // 3*F
    float* vA    = dAll + 3 * F;                   // CAP
    float* vB    = vA + CAP;                       // CAP
    float* cand  = vB + CAP;                       // MAXBT
    int*   plS   = (int*)(cand + MAXBT);           // MAXBT
    int*   fsS   = plS + MAXBT;                    // MAXBT
    float* redV  = (float*)(fsS + MAXBT);          // NT
    int*   redIs = (int*)(redV + NT);              // NT
    unsigned char* cls = (unsigned char*)(redIs + NT);  // S bytes

    const int tid  = threadIdx.x;
    const int lane = tid & 31;
    const int nBT  = 4 * T;                        // 240
    const bool isRed = (tid < nBT);

    // ---------------- prologue ----------------
    for (int t = tid; t < F; t += NT) {
        float ab = acts[2 * t + 0];
        float ad = acts[2 * t + 1];
        dAll[3 * t + 0] = logf(((1.0f - ab) - ad) / 15.0f);   // exact ref order
        dAll[3 * t + 1] = logf(ab);
        dAll[3 * t + 2] = logf(ad);
    }
    const float v0 = -logf((float)S);
    for (int s = tid; s < CAP; s += NT) vA[s] = v0;           // pad incl.
    for (int s = tid; s < S; s += NT) cls[s] = (unsigned char)ptr_g[s];
    if (tid < nBT) { plS[tid] = pl_g[tid]; fsS[tid] = fs_g[tid]; }
    if (tid == 0) redIs[0] = 0;                    // handler-list counter
    __syncthreads();

    int rb = 0, rfs = 0, rcf = 0, plReg = 0, cbase = 0, lo = 0, W = 0;
    const float* colG = lt_g;
    float LTreg[MAXBAND];
    if (isRed) {
        rb    = tid / T;
        int rj = tid - rb * T;
        rfs   = fsS[tid];
        rcf   = ptr_g[rfs];
        plReg = plS[tid];
        cbase = rb * T;
        cls[rfs] |= 4;                              // mark first state
        colG  = lt_g + (rb * T) * T + rj;           // column j of beat b
        int loi = -1, hii = -1;
        for (int i = 0; i < T; ++i) {
            float x = colG[i * T];
            if (x > -1e29f) { if (loi < 0) loi = i; hii = i; }
        }
        lo = loi; W = hii - loi + 1;
#pragma unroll
        for (int k = 0; k < MAXBAND; ++k)
            LTreg[k] = (k < W) ? colG[(lo + k) * T] : -1e30f;
        int lastS = pl_g[(((rb + 1) & 3) * T) + rj];
        for (int s = rfs; s <= lastS; ++s) g_bj[s] = (unsigned short)tid;
    }
    __syncthreads();

    // classify quads; push special-quad non-first states to handler list
    unsigned pureMask = 0;
#pragma unroll
    for (int g = 0; g < QPT; ++g) {
        int qb = 4 * (tid + g * NT);
        bool pure = true;
        int nloc = 0; int loc[4];
#pragma unroll
        for (int j = 0; j < 4; ++j) {
            int s = qb + j;
            if (s >= S) { pure = false; continue; }
            unsigned char m = cls[s];
            if ((m & 7u) != 0u || s == 0) pure = false;
        }
        if (pure) pureMask |= 1u << g;
        else {
#pragma unroll
            for (int j = 0; j < 4; ++j) {
                int s = qb + j;
                if (s < S && !(cls[s] & 4))
                    loc[nloc++] = s | ((int)(cls[s] & 3) << 16);
            }
            if (nloc) {
                int base = atomicAdd(&redIs[0], nloc);
                for (int i = 0; i < nloc; ++i) g_hlist[base + i] = loc[i];
            }
        }
    }
    __syncthreads();
    const int hTotal = redIs[0];
    int hent[HSLOTS];
    unsigned hmask = 0;
#pragma unroll
    for (int k = 0; k < HSLOTS; ++k) {
        int idx = tid + k * NT;
        if (idx < hTotal) { hent[k] = g_hlist[idx]; hmask |= 1u << k; }
        else hent[k] = 0;
    }
    __syncthreads();

    // ---------------- main frame loop ----------------
    float* vCur = vA;
    float* vNxt = vB;
    for (int t = 0; t < F; ++t) {
        const float d0 = dAll[3 * t + 0];
        const float d1 = dAll[3 * t + 1];
        const float d2 = dAll[3 * t + 2];

        if (isRed) cand[tid] = vCur[plReg];
        __syncthreads();                            // cand visible to reduction

        if (isRed) {
            // banded max-plus reduction, strict > ascending == first argmax
            float best = cand[cbase + lo] + LTreg[0];
            int   arg  = lo;
#pragma unroll
            for (int k = 1; k < MAXBAND; ++k) {
                if (k < W) {
                    float sc = cand[cbase + lo + k] + LTreg[k];
                    bool p = sc > best;
                    best = p ? sc : best;
                    arg  = p ? (lo + k) : arg;
                }
            }
            for (int k = MAXBAND; k < W; ++k) {      // safety tail (normally empty)
                float sc = cand[cbase + lo + k] + colG[(lo + k) * T];
                bool p = sc > best;
                best = p ? sc : best;
                arg  = p ? (lo + k) : arg;
            }
            g_bpf[(t << 8) + tid] = plS[cbase + arg];
            float df = (rcf == 1) ? d1 : ((rcf == 2) ? d2 : d0);
            vNxt[rfs] = best + df;
        }

        // pure-quad shift-sweep (all adds use d0; store gated by pureMask)
#pragma unroll
        for (int g = 0; g < QPT; ++g) {
            const int base = 4 * (tid + g * NT);
            float4 Q = *(const float4*)(vCur + base);
            float wl = __shfl_up_sync(0xffffffffu, Q.w, 1);
            if (lane == 0) wl = vCur[base - 1];     // dead if quad special
            float4 Nq;
            Nq.x = wl  + d0;
            Nq.y = Q.x + d0;
            Nq.z = Q.y + d0;
            Nq.w = Q.z + d0;
            if ((pureMask >> g) & 1u)
                *(float4*)(vNxt + base) = Nq;
        }

        // handler slots: special-quad non-first states
#pragma unroll
        for (int k = 0; k < HSLOTS; ++k) {
            if ((hmask >> k) & 1u) {
                int e = hent[k];
                int s = e & 0xFFFF;
                int c = e >> 16;
                float d = (c == 1) ? d1 : ((c == 2) ? d2 : d0);
                vNxt[s] = vCur[s - 1] + d;
            }
        }
        __syncthreads();
        float* tmp = vCur; vCur = vNxt; vNxt = tmp;
    }

    // ---------------- final argmax (first occurrence on ties) ----------------
    float bv = -3.0e38f;
    int   bi = 0x7fffffff;
    for (int s = tid; s < S; s += NT) {
        float v = vCur[s];
        if (v > bv) { bv = v; bi = s; }
    }
    redV[tid] = bv; redIs[tid] = bi;
    __syncthreads();

    if (tid == 0) {
        for (int k = 1; k < NT; ++k) {
            float v = redV[k]; int i = redIs[k];
            if (v > bv || (v == bv && i < bi)) { bv = v; bi = i; }
        }
        // backtrace with run-length decoding
        int s = bi;
        int t = F - 1;
        if (outMode) outF[t] = (float)s; else outI[t] = s;
        while (t > 0) {
            int bj  = g_bj[s];
            int fsv = fsS[bj];
            if (s > fsv) {
                int k = s - fsv; if (k > t) k = t;
                if (outMode) { for (int m = 1; m <= k; ++m) outF[t - m] = (float)(s - m); }
                else         { for (int m = 1; m <= k; ++m) outI[t - m] = s - m; }
                s -= k; t -= k;
            } else {
                s = g_bpf[(t << 8) + bj];
                --t;
                if (outMode) outF[t] = (float)s; else outI[t] = s;
            }
        }
        if (outMode && outSize > F) outF[F] = bv;
    }
}

// ------------------------------------------------------------------
extern "C" void kernel_launch(void* const* d_in, const int* in_sizes, int n_in,
                              void* d_out, int out_size)
{
    const float* acts = (const float*)d_in[0];   // [F,2]
    const float* lt   = (const float*)d_in[1];   // [4,T,T]
    const int*   pl   = (const int*)d_in[2];     // [4,T]
    const int*   fs   = (const int*)d_in[3];     // [4,T]
    const int*   ptr  = (const int*)d_in[4];     // [S]

    const int F = in_sizes[0] / 2;
    const int T = in_sizes[2] / 4;
    const int S = in_sizes[4];

    size_t smemBytes =
        (size_t)4 * (3 * F)            // dAll
      + (size_t)4 * CAP * 2            // vA, vB
      + (size_t)4 * (MAXBT * 3)        // cand, plS, fsS
      + (size_t)4 * (NT * 2)           // redV, redIs
      + (size_t)S + 64;                // cls + pad

    int outMode = (out_size == F) ? 0 : 1;

    cudaFuncSetAttribute(viterbi_kernel,
                         cudaFuncAttributeMaxDynamicSharedMemorySize,
                         (int)smemBytes);

    viterbi_kernel<<<1, NT, smemBytes>>>(acts, lt, pl, fs, ptr, S, T, F,
                                         (float*)d_out, (int*)d_out,
                                         outMode, out_size);
}